// round 17
// baseline (speedup 1.0000x reference)
#include <cuda_runtime.h>
#include <math.h>

// Problem constants
#define T_STEPS 16384
#define HDIM    1024
#define XDIM    256

// Recurrent kernel config: 32 CTAs x 512 threads, 2 rows/warp, coalesced h
#define NCTA          32
#define ROWS_PER_CTA  32    // HDIM / NCTA
#define RNN_THREADS   512   // 16 warps
#define WATCHDOG_POLLS 1000000   // ~0.3 s at ~300cyc poll period

// Scratch (device globals: allocation-free per harness rules)
__device__ float g_bx[(size_t)T_STEPS * HDIM];   // Bx_c precompute, 64 MB
__device__ int   g_cnt[T_STEPS];                 // packed per-step counters (proven)
__device__ int   g_abort;

// ---------------------------------------------------------------------------
// helpers
// ---------------------------------------------------------------------------
__device__ __forceinline__ int ld_acquire_gpu(const int* p) {
    int v;
    asm volatile("ld.acquire.gpu.global.s32 %0, [%1];" : "=r"(v) : "l"(p) : "memory");
    return v;
}

__device__ __forceinline__ void red_release_add(int* p, int v) {
    asm volatile("red.release.gpu.global.add.s32 [%0], %1;" :: "l"(p), "r"(v) : "memory");
}

__device__ __forceinline__ int ldcg_i32(const int* p) {
    int v;
    asm volatile("ld.global.cg.s32 %0, [%1];" : "=r"(v) : "l"(p) : "memory");
    return v;
}

__device__ __forceinline__ void stg_i32(int* p, int v) {
    asm volatile("st.global.s32 [%0], %1;" :: "l"(p), "r"(v) : "memory");
}

__device__ __forceinline__ float warp_sum(float v) {
#pragma unroll
    for (int s = 16; s > 0; s >>= 1)
        v += __shfl_xor_sync(0xffffffffu, v, s);
    return v;
}

__device__ __forceinline__ float fast_tanh(float x) {
    // tanh(x) = 1 - 2/(exp(2x)+1); MUFU-based, ~1e-6 rel error (validated).
    return 1.0f - __fdividef(2.0f, __expf(2.0f * x) + 1.0f);
}

// ---------------------------------------------------------------------------
// 0) zero counters + abort (graph replays reuse device globals -> re-init)
// ---------------------------------------------------------------------------
__global__ void init_cnt_kernel() {
    int i = blockIdx.x * blockDim.x + threadIdx.x;
    g_cnt[i] = 0;
    if (i == 0) g_abort = 0;
}

// ---------------------------------------------------------------------------
// 1) Bx_c = x_seq @ B^T + c   (T x H), fp32 tiled GEMM
// ---------------------------------------------------------------------------
__global__ __launch_bounds__(256) void gemm_bx_kernel(
    const float* __restrict__ x,   // (T, 256)
    const float* __restrict__ B,   // (1024, 256)
    const float* __restrict__ c)   // (1024,)
{
    __shared__ float xsT[32][132];
    __shared__ float bsT[32][68];

    const int bj  = blockIdx.x * 64;
    const int bt  = blockIdx.y * 128;
    const int tid = threadIdx.x;
    const int tx  = tid & 15;
    const int ty  = tid >> 4;

    float acc[8][4];
#pragma unroll
    for (int i = 0; i < 8; i++)
#pragma unroll
        for (int j = 0; j < 4; j++) acc[i][j] = 0.0f;

    for (int k0 = 0; k0 < XDIM; k0 += 32) {
#pragma unroll
        for (int i = 0; i < 4; i++) {
            int idx = tid + i * 256;
            int r   = idx >> 3;
            int kk4 = (idx & 7) * 4;
            float4 v = *(const float4*)&x[(size_t)(bt + r) * XDIM + k0 + kk4];
            xsT[kk4 + 0][r] = v.x; xsT[kk4 + 1][r] = v.y;
            xsT[kk4 + 2][r] = v.z; xsT[kk4 + 3][r] = v.w;
        }
#pragma unroll
        for (int i = 0; i < 2; i++) {
            int idx = tid + i * 256;
            int r   = idx >> 3;
            int kk4 = (idx & 7) * 4;
            float4 v = *(const float4*)&B[(size_t)(bj + r) * XDIM + k0 + kk4];
            bsT[kk4 + 0][r] = v.x; bsT[kk4 + 1][r] = v.y;
            bsT[kk4 + 2][r] = v.z; bsT[kk4 + 3][r] = v.w;
        }
        __syncthreads();

#pragma unroll
        for (int kk = 0; kk < 32; kk++) {
            float xr[8], br[4];
#pragma unroll
            for (int i = 0; i < 8; i++) xr[i] = xsT[kk][ty * 8 + i];
#pragma unroll
            for (int j = 0; j < 4; j++) br[j] = bsT[kk][tx * 4 + j];
#pragma unroll
            for (int i = 0; i < 8; i++)
#pragma unroll
                for (int j = 0; j < 4; j++)
                    acc[i][j] = fmaf(xr[i], br[j], acc[i][j]);
        }
        __syncthreads();
    }

#pragma unroll
    for (int i = 0; i < 8; i++) {
        int t = bt + ty * 8 + i;
#pragma unroll
        for (int j = 0; j < 4; j++) {
            int col = bj + tx * 4 + j;
            g_bx[(size_t)t * HDIM + col] = acc[i][j] + c[col];
        }
    }
}

// ---------------------------------------------------------------------------
// 2) persistent recurrent kernel: 32 CTAs, coalesced h, fast acquire-poll.
//    CTA b owns rows [32b, 32b+32); warp w owns rows 32b+w and 32b+16+w.
//    Lane l holds A[row, 128i+4l..+3] (i=0..7) for both rows -> every warp
//    LDG.128 of h covers one contiguous 512B span (nL=4, R16-proven).
//    Poll: bare dependent acquire-load loop (~320cyc natural period);
//    32 pollers => 0.10 reads/cyc, under the 0.14 proven-live threshold.
// ---------------------------------------------------------------------------
__global__ __launch_bounds__(RNN_THREADS, 1) void rnn_scan_kernel(
    const float* __restrict__ A_raw,  // (1024, 1024)
    const float* __restrict__ h0,     // (1024,)
    float* __restrict__ out)          // (16384, 1024)
{
    __shared__ int s_abort;
    const int b  = blockIdx.x;
    const int w  = threadIdx.x >> 5;
    const int l  = threadIdx.x & 31;
    const int r0 = b * ROWS_PER_CTA + w;        // rows 0..15 of the CTA block
    const int r1 = r0 + 16;                     // rows 16..31

    if (threadIdx.x == 0) s_abort = 0;

    // Load A rows r0, r1 (coalesced per-lane columns 128i+4l..+3),
    // folding A = 0.9*I + 0.1*A_raw.
    float4 a0[8], a1[8];
#pragma unroll
    for (int i = 0; i < 8; i++) {
        int col  = 128 * i + 4 * l;
        float4 v = *(const float4*)&A_raw[(size_t)r0 * HDIM + col];
        v.x *= 0.1f; v.y *= 0.1f; v.z *= 0.1f; v.w *= 0.1f;
        int d = r0 - col;
        if (d == 0) v.x += 0.9f;
        else if (d == 1) v.y += 0.9f;
        else if (d == 2) v.z += 0.9f;
        else if (d == 3) v.w += 0.9f;
        a0[i] = v;

        float4 u = *(const float4*)&A_raw[(size_t)r1 * HDIM + col];
        u.x *= 0.1f; u.y *= 0.1f; u.z *= 0.1f; u.w *= 0.1f;
        int e = r1 - col;
        if (e == 0) u.x += 0.9f;
        else if (e == 1) u.y += 0.9f;
        else if (e == 2) u.z += 0.9f;
        else if (e == 3) u.w += 0.9f;
        a1[i] = u;
    }
    __syncthreads();

    const float* hprev = h0;

    for (int t = 0; t < T_STEPS; t++) {
        // bias prefetch (independent of h -> overlaps wait)
        float bxv = 0.0f;
        if (l == 0)       bxv = g_bx[(size_t)t * HDIM + r0];
        else if (l == 16) bxv = g_bx[(size_t)t * HDIM + r1];

        if (t > 0) {
            if (threadIdx.x == 0) {
                const int* cp = &g_cnt[t - 1];
                int polls = 0;
                for (;;) {
                    if (ld_acquire_gpu(cp) >= NCTA) break;  // ~320cyc period
                    if ((++polls & 63) == 0) {              // rare slow path
                        if (ldcg_i32(&g_abort) || polls > WATCHDOG_POLLS) {
                            stg_i32(&g_abort, 1);
                            s_abort = 1;
                            break;
                        }
                    }
                }
            }
            __syncthreads();
            if (s_abort) return;   // uniform exit: fallback recomputes
            hprev = out + (size_t)(t - 1) * HDIM;
        }

        // dot products: warp instruction i covers h[128i..128i+127] (512B)
        const float4* h4 = (const float4*)hprev;
        float p0 = 0.f, p1 = 0.f, q0 = 0.f, q1 = 0.f;
#pragma unroll
        for (int i = 0; i < 8; i++) {
            float4 hv = h4[32 * i + l];
            p0 = fmaf(a0[i].x, hv.x, p0);
            p1 = fmaf(a0[i].y, hv.y, p1);
            p0 = fmaf(a0[i].z, hv.z, p0);
            p1 = fmaf(a0[i].w, hv.w, p1);
            q0 = fmaf(a1[i].x, hv.x, q0);
            q1 = fmaf(a1[i].y, hv.y, q1);
            q0 = fmaf(a1[i].z, hv.z, q0);
            q1 = fmaf(a1[i].w, hv.w, q1);
        }
        float acc0 = warp_sum(p0 + p1);
        float acc1 = warp_sum(q0 + q1);

        if (l == 0) {
            out[(size_t)t * HDIM + r0] = fast_tanh(acc0 + bxv);
        } else if (l == 16) {
            out[(size_t)t * HDIM + r1] = fast_tanh(acc1 + bxv);
        }

        __syncthreads();  // all 32 rows stored before publishing
        if (threadIdx.x == 0) red_release_add(&g_cnt[t], 1);
    }
}

// ---------------------------------------------------------------------------
// 3) fallback: single-CTA full recompute; runs only if g_abort was set.
// ---------------------------------------------------------------------------
__global__ __launch_bounds__(1024) void fallback_scan_kernel(
    const float* __restrict__ A_raw,
    const float* __restrict__ h0,
    float* __restrict__ out)
{
    if (g_abort == 0) return;

    __shared__ float h[HDIM];
    __shared__ float hn[HDIM];
    const int tid = threadIdx.x;
    const int w   = tid >> 5;
    const int l   = tid & 31;

    h[tid] = h0[tid];
    __syncthreads();

    for (int t = 0; t < T_STEPS; t++) {
        for (int r = w; r < HDIM; r += 32) {
            const float* Ar = A_raw + (size_t)r * HDIM;
            float acc = 0.0f;
#pragma unroll 8
            for (int k = l; k < HDIM; k += 32)
                acc = fmaf(Ar[k], h[k], acc);
#pragma unroll
            for (int s = 16; s > 0; s >>= 1)
                acc += __shfl_xor_sync(0xffffffffu, acc, s);
            if (l == 0) {
                float v = tanhf(0.1f * acc + 0.9f * h[r] +
                                g_bx[(size_t)t * HDIM + r]);
                hn[r] = v;
                out[(size_t)t * HDIM + r] = v;
            }
        }
        __syncthreads();
        h[tid] = hn[tid];
        __syncthreads();
    }
}

// ---------------------------------------------------------------------------
// launch
// ---------------------------------------------------------------------------
extern "C" void kernel_launch(void* const* d_in, const int* in_sizes, int n_in,
                              void* d_out, int out_size) {
    const float* x_seq = (const float*)d_in[0];  // (16384, 256)
    const float* h0    = (const float*)d_in[1];  // (1024,)
    const float* A_raw = (const float*)d_in[2];  // (1024, 1024)
    const float* B     = (const float*)d_in[3];  // (1024, 256)
    const float* c     = (const float*)d_in[4];  // (1024,)
    float* out = (float*)d_out;                  // (16384, 1024)

    init_cnt_kernel<<<16, 1024>>>();
    gemm_bx_kernel<<<dim3(HDIM / 64, T_STEPS / 128), 256>>>(x_seq, B, c);
    rnn_scan_kernel<<<NCTA, RNN_THREADS>>>(A_raw, h0, out);
    fallback_scan_kernel<<<1, 1024>>>(A_raw, h0, out);
}